// round 10
// baseline (speedup 1.0000x reference)
#include <cuda_runtime.h>
#include <math.h>

// Problem constants (fixed by reference setup_inputs)
#define BATCH 64
#define NPTS  16384
#define DIM   16
#define GRID  128                       // 2 blocks per batch, single wave
#define T1    512                       // 16 warps = 8 producer/consumer pairs
#define NPAIR 72                        // packed f32x2 triangle entries (total)
#define NHALF 36                        // per-warp half triangle
#define NPACKF (NPAIR * 2)              // 144 floats
#define ROWS_PER_BLOCK (NPTS / 2)       // 8192
#define ROWS_PER_PAIR  (ROWS_PER_BLOCK / 8)  // 1024 rows per warp pair
#define ITERS (ROWS_PER_PAIR / 32)      // 32 iters x 32 rows
#define DEPTH 4
#define STAGE_BYTES 2048                // 32 rows x 64 B
#define DYN_SMEM (8 * DEPTH * STAGE_BYTES)  // 64 KB (8 pairs)
#define NTERMS 9

__device__ float g_scratch[GRID * NPACKF];
__device__ unsigned int g_arrive;       // monotonic across graph replays

#define PACK2(d, lo, hi) \
    asm("mov.b64 %0, {%1, %2};" : "=l"(d) : "f"(lo), "f"(hi))
#define FMA2(d, a, b) \
    asm("fma.rn.f32x2 %0, %1, %2, %0;" : "+l"(d) : "l"(a), "l"(b))
#define ADD2(d, a, b) \
    asm("add.rn.f32x2 %0, %1, %2;" : "=l"(d) : "l"(a), "l"(b))

#define CP_ASYNC16(dst_u32, src_ptr) \
    asm volatile("cp.async.ca.shared.global [%0], [%1], 16;" :: "r"(dst_u32), "l"(src_ptr) : "memory")
#define CP_COMMIT() asm volatile("cp.async.commit_group;" ::: "memory")
#define CP_WAIT(n)  asm volatile("cp.async.wait_group %0;" :: "n"(n) : "memory")
#define BAR_SYNC(id, cnt) \
    asm volatile("bar.sync %0, %1;" :: "r"(id), "r"(cnt) : "memory")

__device__ __forceinline__ unsigned int ld_acq(const unsigned int* p) {
    unsigned int v;
    asm volatile("ld.acquire.gpu.u32 %0, [%1];" : "=r"(v) : "l"(p));
    return v;
}

// ---------------------------------------------------------------------------
// Fused kernel, warp-pair specialized phase 1.
//   Pair p = warps (2p, 2p+1). Even warp: issues cp.async for the shared
//   stage ring AND accumulates triangle rows i=11..15 (36 f32x2 pairs).
//   Odd warp: accumulates rows i=0..10 (36 pairs, needs only quarters 0..2).
//   One named bar.sync per iter; producer issues new stage AFTER the bar
//   (write targets stage (it+3)%4, reads target stage it%4 -> race-free).
//   acc = 72 regs/thread -> ~120 total -> 16 warps/SM (4/SMSP), 2x TLP.
// Grid spin barrier; phase 2 (blocks 0..63) logm + power + FC + L2 norm.
// ---------------------------------------------------------------------------
__global__ __launch_bounds__(T1, 1) void soap_fused(
    const float* __restrict__ x, const float* __restrict__ W,
    const float* __restrict__ bias, const float* __restrict__ p,
    float* __restrict__ out) {

    extern __shared__ float4 stages[];   // [8 pairs][DEPTH][128 float4]

    __shared__ unsigned long long red[16][NHALF];       // 4.6 KB
    __shared__ float Em[16][17];
    __shared__ float Pm[2][16][17];
    __shared__ float mf[256];
    __shared__ float fvv[256];
    __shared__ float warpsum[8];
    __shared__ float s_nrm;

    const int tid = threadIdx.x;
    const int w = tid >> 5;
    const int l = tid & 31;
    const int pair = w >> 1;
    const bool producer = ((w & 1) == 0);
    const int barid = pair + 1;          // named barriers 1..8 (0 = syncthreads)
    const int blk = blockIdx.x;
    const int b = blk >> 1;
    const int s = blk & 1;

    // ---------------- Phase 1: cov partial -------------------------------
    const float4* __restrict__ src = (const float4*)x +
        ((size_t)b * NPTS + (size_t)s * ROWS_PER_BLOCK + (size_t)pair * ROWS_PER_PAIR) * 4
        + l;

    const unsigned int tbase =
        (unsigned int)__cvta_generic_to_shared(stages) + (unsigned int)(pair * DEPTH * STAGE_BYTES);
    // swizzled per-lane dst offset (verified R3): row r=8k+(l>>2), chunk q=l&3
    const unsigned int c0 =
        (unsigned int)((l >> 2) * 64 + ((((l & 3) + (l >> 3)) & 3) * 16));
    const char* rbase = (const char*)stages + pair * DEPTH * STAGE_BYTES;

    unsigned long long acc[NHALF];
#pragma unroll
    for (int c = 0; c < NHALF; c++) acc[c] = 0ull;

    // producer prologue: stages 0..DEPTH-2
    if (producer) {
#pragma unroll
        for (int st = 0; st < DEPTH - 1; st++) {
            const float4* sp = src + st * 128;
            const unsigned int t = tbase + (unsigned int)(st * STAGE_BYTES) + c0;
            CP_ASYNC16(t,        sp);
            CP_ASYNC16(t + 512,  sp + 32);
            CP_ASYNC16(t + 1024, sp + 64);
            CP_ASYNC16(t + 1536, sp + 96);
            CP_COMMIT();
        }
    }

#pragma unroll 2
    for (int it = 0; it < ITERS; ++it) {
        // producer: ensure stage it complete (exact tail waits)
        if (producer) {
            if (it < ITERS - 2)       { CP_WAIT(DEPTH - 2); }
            else if (it == ITERS - 2) { CP_WAIT(1); }
            else                      { CP_WAIT(0); }
        }
        BAR_SYNC(barid, 64);   // publish stage it to the pair

        // producer: issue stage it+DEPTH-1 (after bar -> no race with reader)
        if (producer && (it + DEPTH - 1 < ITERS)) {
            const float4* sp = src + (it + DEPTH - 1) * 128;
            const unsigned int t =
                tbase + (unsigned int)(((it + DEPTH - 1) & (DEPTH - 1)) * STAGE_BYTES) + c0;
            CP_ASYNC16(t,        sp);
            CP_ASYNC16(t + 512,  sp + 32);
            CP_ASYNC16(t + 1024, sp + 64);
            CP_ASYNC16(t + 1536, sp + 96);
            CP_COMMIT();
        }

        const char* base = rbase + (it & (DEPTH - 1)) * STAGE_BYTES + l * 64;

        if (producer) {
            // half B: triangle rows i=11..15, needs full row
            const float4 r0 = *(const float4*)(base + (((0 + (l >> 1)) & 3) * 16));
            const float4 r1 = *(const float4*)(base + (((1 + (l >> 1)) & 3) * 16));
            const float4 r2 = *(const float4*)(base + (((2 + (l >> 1)) & 3) * 16));
            const float4 r3 = *(const float4*)(base + (((3 + (l >> 1)) & 3) * 16));
            float xv[16];
            xv[0]=r0.x; xv[1]=r0.y; xv[2]=r0.z; xv[3]=r0.w;
            xv[4]=r1.x; xv[5]=r1.y; xv[6]=r1.z; xv[7]=r1.w;
            xv[8]=r2.x; xv[9]=r2.y; xv[10]=r2.z; xv[11]=r2.w;
            xv[12]=r3.x; xv[13]=r3.y; xv[14]=r3.z; xv[15]=r3.w;
            unsigned long long xp[8];
#pragma unroll
            for (int k = 0; k < 8; k++) PACK2(xp[k], xv[2 * k], xv[2 * k + 1]);
            int bcnt = 0;
#pragma unroll
            for (int i = 11; i < 16; i++) {
                unsigned long long bc;
                PACK2(bc, xv[i], xv[i]);
                const int np = (i + 2) >> 1;
#pragma unroll
                for (int jp = 0; jp < np; jp++) FMA2(acc[bcnt + jp], bc, xp[jp]);
                bcnt += np;  // 6+7+7+8+8 = 36
            }
        } else {
            // half A: triangle rows i=0..10, needs quarters 0..2 only
            const float4 r0 = *(const float4*)(base + (((0 + (l >> 1)) & 3) * 16));
            const float4 r1 = *(const float4*)(base + (((1 + (l >> 1)) & 3) * 16));
            const float4 r2 = *(const float4*)(base + (((2 + (l >> 1)) & 3) * 16));
            float xv[12];
            xv[0]=r0.x; xv[1]=r0.y; xv[2]=r0.z; xv[3]=r0.w;
            xv[4]=r1.x; xv[5]=r1.y; xv[6]=r1.z; xv[7]=r1.w;
            xv[8]=r2.x; xv[9]=r2.y; xv[10]=r2.z; xv[11]=r2.w;
            unsigned long long xp[6];
#pragma unroll
            for (int k = 0; k < 6; k++) PACK2(xp[k], xv[2 * k], xv[2 * k + 1]);
            int bcnt = 0;
#pragma unroll
            for (int i = 0; i < 11; i++) {
                unsigned long long bc;
                PACK2(bc, xv[i], xv[i]);
                const int np = (i + 2) >> 1;
#pragma unroll
                for (int jp = 0; jp < np; jp++) FMA2(acc[bcnt + jp], bc, xp[jp]);
                bcnt += np;  // ends at 36
            }
        }
    }

    // butterfly reduce within warp (packed adds)
#pragma unroll
    for (int c = 0; c < NHALF; c++) {
        unsigned long long v = acc[c];
#pragma unroll
        for (int off = 16; off >= 1; off >>= 1) {
            unsigned long long o = __shfl_xor_sync(0xFFFFFFFFu, v, off);
            ADD2(v, v, o);
        }
        if (l == 0) red[w][c] = v;
    }
    __syncthreads();

    // cross-warp sum: global pair c -> half h=(c>=36), warps (h?0:1)+2k
    if (tid < NPACKF) {
        const int c = tid >> 1;
        const int e = tid & 1;
        const int h = (c >= NHALF) ? 1 : 0;
        const int lc = c - NHALF * h;
        const int w0 = h ? 0 : 1;   // half B lives in even warps, half A in odd
        const float* redf = (const float*)red;   // [16][36][2]
        float v = 0.f;
#pragma unroll
        for (int k = 0; k < 8; k++) v += redf[(w0 + 2 * k) * (NHALF * 2) + lc * 2 + e];
        g_scratch[blk * NPACKF + tid] = v;
    }
    __threadfence();
    __syncthreads();

    // ---------------- Grid spin barrier (monotonic ticket) ----------------
    if (tid == 0) {
        const unsigned int t = atomicAdd(&g_arrive, 1u);
        const unsigned int target = (t / GRID + 1u) * GRID;
        while (ld_acq(&g_arrive) < target) __nanosleep(32);
    }
    __syncthreads();

    // ---------------- Phase 2: finish (blocks 0..63) -----------------------
    if (blk >= BATCH) return;
    const int b2 = blk;
    const bool act = (tid < 256);

    if (tid < 136) {
        int c = tid, i = 0;
        while (c >= i + 1) { c -= i + 1; i++; }
        const int j = c;
        int bs = 0;
#pragma unroll
        for (int r = 0; r < 16; r++) if (r < i) bs += (r + 2) >> 1;
        const int fidx = (bs + (j >> 1)) * 2 + (j & 1);
        float v = g_scratch[(b2 * 2 + 0) * NPACKF + fidx] +
                  g_scratch[(b2 * 2 + 1) * NPACKF + fidx];
        v *= (1.0f / (float)NPTS);
        const float e = v - (i == j ? 1.0f : 0.0f);
        Em[i][j] = e;
        Em[j][i] = e;
    }
    __syncthreads();

    const int i = (tid >> 4) & 15;
    const int j = tid & 15;
    float macc = 0.f;
    if (act) {
        const float e0 = Em[i][j];
        Pm[0][i][j] = e0;
        macc = e0;
    }
    __syncthreads();

    int cur = 0;
#pragma unroll
    for (int k = 2; k <= NTERMS; k++) {
        if (act) {
            float a = 0.f;
#pragma unroll
            for (int ll = 0; ll < 16; ll++) a = fmaf(Pm[cur][i][ll], Em[ll][j], a);
            Pm[cur ^ 1][i][j] = a;
            const float coef = ((k & 1) ? 1.0f : -1.0f) / (float)k;
            macc = fmaf(coef, a, macc);
        }
        cur ^= 1;
        __syncthreads();
    }

    if (act) {
        const float pe = p[0];
        const float av = fabsf(macc);
        float mag = 0.0f;
        if (av > 0.0f) mag = exp2f(pe * log2f(av));
        mf[tid] = (macc < 0.0f) ? -mag : mag;
    }
    __syncthreads();

    // FC (coalesced): 16 warps, warp w does rows r = w, w+16, ...
    {
        const float4* __restrict__ mv = (const float4*)mf;
        const float4 ma = mv[l];
        const float4 mb = mv[l + 32];
#pragma unroll 4
        for (int r = w; r < 256; r += 16) {
            const float4* __restrict__ Wr = (const float4*)(W + (size_t)r * 256);
            const float4 wa = Wr[l];
            const float4 wb = Wr[l + 32];
            float a = wa.x * ma.x;
            a = fmaf(wa.y, ma.y, a);
            a = fmaf(wa.z, ma.z, a);
            a = fmaf(wa.w, ma.w, a);
            a = fmaf(wb.x, mb.x, a);
            a = fmaf(wb.y, mb.y, a);
            a = fmaf(wb.z, mb.z, a);
            a = fmaf(wb.w, mb.w, a);
            a += __shfl_xor_sync(0xFFFFFFFFu, a, 16);
            a += __shfl_xor_sync(0xFFFFFFFFu, a, 8);
            a += __shfl_xor_sync(0xFFFFFFFFu, a, 4);
            a += __shfl_xor_sync(0xFFFFFFFFu, a, 2);
            a += __shfl_xor_sync(0xFFFFFFFFu, a, 1);
            if (l == 0) fvv[r] = a + bias[r];
        }
    }
    __syncthreads();

    // L2 normalize
    if (act) {
        float sq = fvv[tid] * fvv[tid];
        sq += __shfl_xor_sync(0xFFFFFFFFu, sq, 16);
        sq += __shfl_xor_sync(0xFFFFFFFFu, sq, 8);
        sq += __shfl_xor_sync(0xFFFFFFFFu, sq, 4);
        sq += __shfl_xor_sync(0xFFFFFFFFu, sq, 2);
        sq += __shfl_xor_sync(0xFFFFFFFFu, sq, 1);
        if (l == 0) warpsum[w] = sq;
    }
    __syncthreads();
    if (tid == 0) {
        float ss = 0.f;
#pragma unroll
        for (int ww = 0; ww < 8; ww++) ss += warpsum[ww];
        s_nrm = fmaxf(sqrtf(ss), 1e-12f);
    }
    __syncthreads();
    if (act) out[(size_t)b2 * 256 + tid] = fvv[tid] / s_nrm;
}

// ---------------------------------------------------------------------------
// kernel_launch: x [64*16384*16] f32, W [256*256] f32, b [256] f32, p [1] f32.
// out: [64*256] f32.
// ---------------------------------------------------------------------------
extern "C" void kernel_launch(void* const* d_in, const int* in_sizes, int n_in,
                              void* d_out, int out_size) {
    const float* x    = (const float*)d_in[0];
    const float* W    = (const float*)d_in[1];
    const float* bias = (const float*)d_in[2];
    const float* p    = (const float*)d_in[3];
    float* out = (float*)d_out;

    cudaFuncSetAttribute(soap_fused, cudaFuncAttributeMaxDynamicSharedMemorySize, DYN_SMEM);
    soap_fused<<<GRID, T1, DYN_SMEM>>>(x, W, bias, p, out);
}